// round 3
// baseline (speedup 1.0000x reference)
#include <cuda_runtime.h>

#define BATCH 4096
#define SEQ   4096
#define BT    (BATCH * SEQ)
#define HALFB (BATCH / 2)

static __device__ __forceinline__ float ex2f_(float x) {
    float y; asm("ex2.approx.f32 %0, %1;" : "=f"(y) : "f"(x)); return y;
}
static __device__ __forceinline__ float rcpf_(float x) {
    float y; asm("rcp.approx.f32 %0, %1;" : "=f"(y) : "f"(x)); return y;
}
static __device__ __forceinline__ float tanhf_(float x) {
    float y; asm("tanh.approx.f32 %0, %1;" : "=f"(y) : "f"(x)); return y;
}

// ---------------------------------------------------------------------------
// Scan kernel: one thread runs TWO independent GRU chains (rows b, b+2048),
// manually interleaved so each chain's instructions fill the other chain's
// FMA/MUFU latency shadows (single warp per SMSP has no other source of ILP).
//
// Per-step recurrence path (one chain):
//   h -> FMA(s_r)[4] -> MUFU.TANH[16] -> FMA(s_n)[4]
//     -> EX2[16] -> FADD[4] -> RCP[16] -> FMA(h')[4]   = 64 cyc
// z-gate, h-update coefficients (tw, w), x-projections, loads, stores: all
// off-path, overlapped with the other chain.
// h' = (1-z)n + z h, n = 2q-1  ==>  h' = (2-2z)*q + (z*(h+1)-1)
// ---------------------------------------------------------------------------
__global__ void __launch_bounds__(32, 1) gru_scan_kernel(
    const float* __restrict__ xi,    // (B, T, 2): [x, label]
    const float* __restrict__ Wih,   // (3,2) rows r,z,n
    const float* __restrict__ Whh,   // (3,)
    const float* __restrict__ bih,   // (3,)
    const float* __restrict__ bhh,   // (3,)
    float* __restrict__ hraw)        // (B, T) raw h
{
    const int t  = blockIdx.x * 32 + threadIdx.x;   // 0..2047
    const int bA = t;
    const int bB = t + HALFB;

    const float L2E = 1.44269504088896340736f;
    const float S   = -2.0f * L2E;   // tanh(a) = 2*rcp(1+exp2(S*a)) - 1

    const float4* __restrict__ xA = (const float4*)(xi + (size_t)bA * (SEQ * 2));
    const float4* __restrict__ xB = (const float4*)(xi + (size_t)bB * (SEQ * 2));
    const float labA = ((const float*)xA)[1];
    const float labB = ((const float*)xB)[1];

    const float Ar = Wih[0], Br = Wih[1];
    const float Az = Wih[2], Bz = Wih[3];
    const float An = Wih[4], Bn = Wih[5];
    const float Wr = Whh[0], Wz = Whh[1], Wn = Whh[2];

    // Shared (label-independent) folded weights
    const float ar2 = 0.5f * Ar, wr2 = 0.5f * Wr;
    const float az2 = 0.5f * Az, wz2 = 0.5f * Wz;
    const float anS = S * An,    wnS = S * Wn, bnS = S * bhh[2];
    // Per-chain (label-folded) constants
    const float crA = 0.5f * (Br * labA + bih[0] + bhh[0]);
    const float czA = 0.5f * (Bz * labA + bih[1] + bhh[1]);
    const float cnA = S * (Bn * labA + bih[2]);
    const float crB = 0.5f * (Br * labB + bih[0] + bhh[0]);
    const float czB = 0.5f * (Bz * labB + bih[1] + bhh[1]);
    const float cnB = S * (Bn * labB + bih[2]);

    float hA = 0.0f, hB = 0.0f;
    float4* __restrict__ oA = (float4*)(hraw + (size_t)bA * SEQ);
    float4* __restrict__ oB = (float4*)(hraw + (size_t)bB * SEQ);

    // Chunk = 4 steps = 2 float4 of xi per chain; single-ahead prefetch
    float4 cA0 = xA[0], cA1 = xA[1];
    float4 cB0 = xB[0], cB1 = xB[1];

// One interleaved step of both chains. prr/prz/pbn are precomputed x-projections.
#define STEP2(prrA, przA, pbnA, prrB, przB, pbnB, dA, dB) do {         \
        float srA  = fmaf(wr2, hA, (prrA));                            \
        float srB  = fmaf(wr2, hB, (prrB));                            \
        float szA  = fmaf(wz2, hA, (przA));                            \
        float szB  = fmaf(wz2, hB, (przB));                            \
        float ShA  = fmaf(wnS, hA, bnS);                               \
        float ShB  = fmaf(wnS, hB, bnS);                               \
        float trA  = tanhf_(srA);                                      \
        float trB  = tanhf_(srB);                                      \
        float tzA  = tanhf_(szA);                                      \
        float tzB  = tanhf_(szB);                                      \
        float c2A  = fmaf(0.5f, ShA, (pbnA));                          \
        float c2B  = fmaf(0.5f, ShB, (pbnB));                          \
        float zA   = fmaf(0.5f, tzA, 0.5f);                            \
        float zB   = fmaf(0.5f, tzB, 0.5f);                            \
        float wA   = fmaf(zA, hA + 1.0f, -1.0f);                       \
        float wB   = fmaf(zB, hB + 1.0f, -1.0f);                       \
        float twA  = fmaf(-2.0f, zA, 2.0f);                            \
        float twB  = fmaf(-2.0f, zB, 2.0f);                            \
        float snA  = fmaf(trA, 0.5f * ShA, c2A);                       \
        float snB  = fmaf(trB, 0.5f * ShB, c2B);                       \
        float qA   = rcpf_(1.0f + ex2f_(snA));                         \
        float qB   = rcpf_(1.0f + ex2f_(snB));                         \
        hA         = fmaf(twA, qA, wA);                                \
        hB         = fmaf(twB, qB, wB);                                \
        (dA)       = hA;                                               \
        (dB)       = hB;                                               \
    } while (0)

    const int NCH = SEQ / 4;  // 1024 chunks of 4 steps
    for (int c = 0; c < NCH; ++c) {
        const int cn = (c + 1 < NCH) ? (c + 1) : c;
        float4 nA0 = xA[cn * 2], nA1 = xA[cn * 2 + 1];
        float4 nB0 = xB[cn * 2], nB1 = xB[cn * 2 + 1];

        // x-projections for the 4 steps of each chain (x lives at .x / .z)
        float pr0A = fmaf(ar2, cA0.x, crA), pz0A = fmaf(az2, cA0.x, czA), pn0A = fmaf(anS, cA0.x, cnA);
        float pr1A = fmaf(ar2, cA0.z, crA), pz1A = fmaf(az2, cA0.z, czA), pn1A = fmaf(anS, cA0.z, cnA);
        float pr2A = fmaf(ar2, cA1.x, crA), pz2A = fmaf(az2, cA1.x, czA), pn2A = fmaf(anS, cA1.x, cnA);
        float pr3A = fmaf(ar2, cA1.z, crA), pz3A = fmaf(az2, cA1.z, czA), pn3A = fmaf(anS, cA1.z, cnA);
        float pr0B = fmaf(ar2, cB0.x, crB), pz0B = fmaf(az2, cB0.x, czB), pn0B = fmaf(anS, cB0.x, cnB);
        float pr1B = fmaf(ar2, cB0.z, crB), pz1B = fmaf(az2, cB0.z, czB), pn1B = fmaf(anS, cB0.z, cnB);
        float pr2B = fmaf(ar2, cB1.x, crB), pz2B = fmaf(az2, cB1.x, czB), pn2B = fmaf(anS, cB1.x, cnB);
        float pr3B = fmaf(ar2, cB1.z, crB), pz3B = fmaf(az2, cB1.z, czB), pn3B = fmaf(anS, cB1.z, cnB);

        float4 yA, yB;
        STEP2(pr0A, pz0A, pn0A, pr0B, pz0B, pn0B, yA.x, yB.x);
        STEP2(pr1A, pz1A, pn1A, pr1B, pz1B, pn1B, yA.y, yB.y);
        STEP2(pr2A, pz2A, pn2A, pr2B, pz2B, pn2B, yA.z, yB.z);
        STEP2(pr3A, pz3A, pn3A, pr3B, pz3B, pn3B, yA.w, yB.w);

        oA[c] = yA;
        oB[c] = yB;

        cA0 = nA0; cA1 = nA1; cB0 = nB0; cB1 = nB1;
    }
#undef STEP2
}

// ---------------------------------------------------------------------------
// Finish kernel: in-place accurate tanh on raw h, plus labels fill.
// Labels are per-row constants -> one broadcast scalar load per thread
// (no 67MB stream read). DRAM-bound: ~200MB total traffic.
// ---------------------------------------------------------------------------
__global__ void finish_kernel(float4* __restrict__ out,        // BT/4 elems
                              const float* __restrict__ labels,
                              float4* __restrict__ outl)       // or nullptr
{
    const float S = -2.0f * 1.44269504088896340736f;
    int i = blockIdx.x * blockDim.x + threadIdx.x;
    float4 v = out[i];
    v.x = fmaf(2.0f, rcpf_(1.0f + ex2f_(S * v.x)), -1.0f);
    v.y = fmaf(2.0f, rcpf_(1.0f + ex2f_(S * v.y)), -1.0f);
    v.z = fmaf(2.0f, rcpf_(1.0f + ex2f_(S * v.z)), -1.0f);
    v.w = fmaf(2.0f, rcpf_(1.0f + ex2f_(S * v.w)), -1.0f);
    out[i] = v;
    if (outl) {
        const int b = i >> 10;                      // SEQ/4 = 1024 float4/row
        const float lab = __ldg(labels + (size_t)b * SEQ);
        outl[i] = make_float4(lab, lab, lab, lab);
    }
}

extern "C" void kernel_launch(void* const* d_in, const int* in_sizes, int n_in,
                              void* d_out, int out_size)
{
    const float* xi     = (const float*)d_in[0];
    const float* labels = (const float*)d_in[1];
    const float* Wih    = (const float*)d_in[2];
    const float* Whh    = (const float*)d_in[3];
    const float* bih    = (const float*)d_in[4];
    const float* bhh    = (const float*)d_in[5];

    float* out  = (float*)d_out;
    float* outl = (out_size >= 2 * BT) ? (out + (size_t)BT) : (float*)0;

    // 2048 threads = 64 warps; each thread interleaves 2 chains.
    gru_scan_kernel<<<HALFB / 32, 32>>>(xi, Wih, Whh, bih, bhh, out);

    const int N4 = BT / 4;
    finish_kernel<<<N4 / 256, 256>>>((float4*)out, labels, (float4*)outl);
}

// round 4
// speedup vs baseline: 2.2769x; 2.2769x over previous
#include <cuda_runtime.h>

#define BATCH 4096
#define SEQ   4096
#define BT    (BATCH * SEQ)

static __device__ __forceinline__ float ex2f_(float x) {
    float y; asm("ex2.approx.f32 %0, %1;" : "=f"(y) : "f"(x)); return y;
}
static __device__ __forceinline__ float rcpf_(float x) {
    float y; asm("rcp.approx.f32 %0, %1;" : "=f"(y) : "f"(x)); return y;
}
static __device__ __forceinline__ float tanhf_(float x) {
    float y; asm("tanh.approx.f32 %0, %1;" : "=f"(y) : "f"(x)); return y;
}

// ---------------------------------------------------------------------------
// Scan kernel: one thread = one chain (back to R2 config: all 4096 chains in
// flight, 1 warp/SM). Wall time = per-step serial cost; minimize instructions.
//
// All three gates via MUFU.TANH:
//   r = 0.5*tanh(sr)+0.5, z likewise, n = tanh(sn) directly.
//   sn = inn + r*hn = tr*(0.5*hn) + (inn + 0.5*hn)
//   h' = (1-z)*n + z*h = omz*tn + u,  omz = 0.5-0.5*tz,  u = z*h
//
// Recurrence path: FMA(sr)4 -> TANH16 -> FMA(sn)4 -> TANH16 -> FMA(h')4 = 44.
// Everything else (z-gate chain, hhn, c2, u, omz, projections, ld/st) is
// off-path. ~12 recurrence instrs + 3 projection FMAs per step.
// ---------------------------------------------------------------------------
__global__ void __launch_bounds__(32, 1) gru_scan_kernel(
    const float* __restrict__ xi,    // (B, T, 2): [x, label]
    const float* __restrict__ Wih,   // (3,2) rows r,z,n
    const float* __restrict__ Whh,   // (3,)
    const float* __restrict__ bih,   // (3,)
    const float* __restrict__ bhh,   // (3,)
    float* __restrict__ hraw)        // (B, T) raw h
{
    const int b = blockIdx.x * 32 + threadIdx.x;

    const size_t rowoff = (size_t)b * (SEQ * 2);
    const float4* __restrict__ xrow = (const float4*)(xi + rowoff);
    const float label = xi[rowoff + 1];

    const float Ar = Wih[0], Br = Wih[1];
    const float Az = Wih[2], Bz = Wih[3];
    const float An = Wih[4], Bn = Wih[5];
    const float Wr = Whh[0], Wz = Whh[1], Wn = Whh[2];

    // sigmoid(v) = 0.5*tanh(0.5*v)+0.5 -> fold 0.5 into weights
    const float ar2 = 0.5f * Ar, wr2 = 0.5f * Wr;
    const float cr2 = 0.5f * (Br * label + bih[0] + bhh[0]);
    const float az2 = 0.5f * Az, wz2 = 0.5f * Wz;
    const float cz2 = 0.5f * (Bz * label + bih[1] + bhh[1]);
    // n-gate: hhn = 0.5*hn = wn2*h + bn2 ; c2 = inn + 0.5*hn = wn2*h + pxn
    const float wn2 = 0.5f * Wn, bn2 = 0.5f * bhh[2];
    const float anx = An;                       // inn = An*x + cnx
    const float cnx = Bn * label + bih[2] + bn2; // pxn = inn + 0.5*bhn

    float h = 0.0f;
    float4* __restrict__ orow = (float4*)(hraw + (size_t)b * SEQ);

    // 4-step chunks (2 float4 of xi), single-chunk-ahead prefetch.
    float4 c0 = xrow[0], c1 = xrow[1];

#define STEP(pxr, pxz, pxn, dst) do {                          \
        float sr  = fmaf(wr2, h, (pxr));                       \
        float sz  = fmaf(wz2, h, (pxz));                       \
        float hhn = fmaf(wn2, h, bn2);                         \
        float c2  = fmaf(wn2, h, (pxn));                       \
        float tr  = tanhf_(sr);                                \
        float tz  = tanhf_(sz);                                \
        float u   = fmaf(0.5f * h, tz, 0.5f * h);              \
        float omz = fmaf(-0.5f, tz, 0.5f);                     \
        float sn  = fmaf(tr, hhn, c2);                         \
        float tn  = tanhf_(sn);                                \
        h         = fmaf(omz, tn, u);                          \
        (dst)     = h;                                         \
    } while (0)

    const int NCH = SEQ / 4;  // 1024 chunks
    for (int c = 0; c < NCH; ++c) {
        const int cn = (c + 1 < NCH) ? (c + 1) : c;
        float4 n0 = xrow[cn * 2], n1 = xrow[cn * 2 + 1];

        // Hoisted x-projections (independent of h); x at .x/.z of each float4
        float pr0 = fmaf(ar2, c0.x, cr2), pz0 = fmaf(az2, c0.x, cz2), pn0 = fmaf(anx, c0.x, cnx);
        float pr1 = fmaf(ar2, c0.z, cr2), pz1 = fmaf(az2, c0.z, cz2), pn1 = fmaf(anx, c0.z, cnx);
        float pr2 = fmaf(ar2, c1.x, cr2), pz2 = fmaf(az2, c1.x, cz2), pn2 = fmaf(anx, c1.x, cnx);
        float pr3 = fmaf(ar2, c1.z, cr2), pz3 = fmaf(az2, c1.z, cz2), pn3 = fmaf(anx, c1.z, cnx);

        float4 y;
        STEP(pr0, pz0, pn0, y.x);
        STEP(pr1, pz1, pn1, y.y);
        STEP(pr2, pz2, pn2, y.z);
        STEP(pr3, pz3, pn3, y.w);
        orow[c] = y;

        c0 = n0; c1 = n1;
    }
#undef STEP
}

// ---------------------------------------------------------------------------
// Finish kernel: in-place accurate tanh on raw h + labels broadcast fill.
// ---------------------------------------------------------------------------
__global__ void finish_kernel(float4* __restrict__ out,        // BT/4 elems
                              const float* __restrict__ labels,
                              float4* __restrict__ outl)       // or nullptr
{
    const float S = -2.0f * 1.44269504088896340736f;
    int i = blockIdx.x * blockDim.x + threadIdx.x;
    float4 v = out[i];
    v.x = fmaf(2.0f, rcpf_(1.0f + ex2f_(S * v.x)), -1.0f);
    v.y = fmaf(2.0f, rcpf_(1.0f + ex2f_(S * v.y)), -1.0f);
    v.z = fmaf(2.0f, rcpf_(1.0f + ex2f_(S * v.z)), -1.0f);
    v.w = fmaf(2.0f, rcpf_(1.0f + ex2f_(S * v.w)), -1.0f);
    out[i] = v;
    if (outl) {
        const int b = i >> 10;                      // SEQ/4 float4 per row
        const float lab = __ldg(labels + (size_t)b * SEQ);
        outl[i] = make_float4(lab, lab, lab, lab);
    }
}

extern "C" void kernel_launch(void* const* d_in, const int* in_sizes, int n_in,
                              void* d_out, int out_size)
{
    const float* xi     = (const float*)d_in[0];
    const float* labels = (const float*)d_in[1];
    const float* Wih    = (const float*)d_in[2];
    const float* Whh    = (const float*)d_in[3];
    const float* bih    = (const float*)d_in[4];
    const float* bhh    = (const float*)d_in[5];

    float* out  = (float*)d_out;
    float* outl = (out_size >= 2 * BT) ? (out + (size_t)BT) : (float*)0;

    gru_scan_kernel<<<BATCH / 32, 32>>>(xi, Wih, Whh, bih, bhh, out);

    const int N4 = BT / 4;
    finish_kernel<<<N4 / 256, 256>>>((float4*)out, labels, (float4*)outl);
}